// round 6
// baseline (speedup 1.0000x reference)
#include <cuda_runtime.h>
#include <math.h>
#include <stdint.h>

#define TT   4096
#define HID  2048
#define NH   32
#define HD   128
#define PP   4096
#define TP   (TT * PP)
#define NQKV 12288    // 3*PP
#define NFAB 384      // fa(128) | ga(128) | beta(32, cols 256-287; 288-383 zero)

// ---------------- scratch (device globals; no allocations allowed) ----------
__device__ float g_hsr[TT * HID];
__device__ float g_qkvp[TT * NQKV];
__device__ float g_q [TP];
__device__ float g_k [TP];
__device__ float g_v [TP];
__device__ float g_eg[TP];
__device__ float g_g2[TP];
__device__ float g_o [TP];
__device__ float g_fab[TT * NFAB];
__device__ float g_beta[TT * NH];
// transposed + tf32-rounded weights: BT[n][k]
__device__ float g_wqkvT[NQKV * HID];
__device__ float g_wfabT[NFAB * HID];   // rows 288-383 stay zero
__device__ float g_wfbT[PP * HD];
__device__ float g_wgbT[PP * HD];
__device__ float g_woT[HID * PP];

// ---------------- helpers -----------------------------------------------------
__device__ __forceinline__ uint32_t smem_u32(const void* p) {
    uint32_t a;
    asm("{ .reg .u64 t; cvta.to.shared.u64 t, %1; cvt.u32.u64 %0, t; }" : "=r"(a) : "l"(p));
    return a;
}
__device__ __forceinline__ float rna_tf32(float x) {
    uint32_t o, i = __float_as_uint(x);
    asm("cvt.rna.tf32.f32 %0, %1;" : "=r"(o) : "r"(i));
    return __uint_as_float(o);
}
__device__ __forceinline__ void cp_async16(uint32_t dst, const float* src) {
    asm volatile("cp.async.cg.shared.global [%0], [%1], 16;\n"
                 :: "r"(dst), "l"(__cvta_generic_to_global(src)));
}
__device__ __forceinline__ void cp_commit() { asm volatile("cp.async.commit_group;\n" ::: "memory"); }

#define MMA_TF32(d, a, b)                                                      \
    asm volatile("mma.sync.aligned.m16n8k8.row.col.f32.tf32.tf32.f32 "        \
                 "{%0,%1,%2,%3}, {%4,%5,%6,%7}, {%8,%9}, {%0,%1,%2,%3};"      \
                 : "+f"((d)[0]), "+f"((d)[1]), "+f"((d)[2]), "+f"((d)[3])     \
                 : "r"((a)[0]), "r"((a)[1]), "r"((a)[2]), "r"((a)[3]),        \
                   "r"((b)[0]), "r"((b)[1]))

#define LDSM_X4(r, addr)                                                       \
    asm volatile("ldmatrix.sync.aligned.m8n8.x4.shared.b16 {%0,%1,%2,%3}, [%4];" \
                 : "=r"((r)[0]), "=r"((r)[1]), "=r"((r)[2]), "=r"((r)[3])      \
                 : "r"(addr))

// ---------------- tf32 mma.sync GEMM (ldmatrix feed, transposed B) ------------
// C[M, :Nvalid] (stride ldc) = A[M,K] (stride lda) @ BT[N,K]^T (stride ldbt).
// A pre-rounded tf32; BT pre-rounded+transposed. CTA tile 128x128x32, 8 warps.
#define BM 128
#define BN 128
#define BK 32
#define ASTR 36
#define BSTR 36
#define A_STAGE (BM * ASTR)            // 4608 floats
#define B_STAGE (BN * BSTR)            // 4608 floats
#define STAGE_F (A_STAGE + B_STAGE)    // 9216 floats
#define NSTAGE 3
#define GEMM_SMEM (NSTAGE * STAGE_F * 4)   // 110592 bytes

__global__ __launch_bounds__(256, 2) void mma_gemm(const float* __restrict__ A, int lda,
                                                   const float* __restrict__ BT, int ldbt,
                                                   float* __restrict__ C, int ldc,
                                                   int Nvalid, int K, int round_limit) {
    extern __shared__ float sm[];
    const uint32_t sb = smem_u32(sm);

    const int tid = threadIdx.x;
    const int wid = tid >> 5, lane = tid & 31;
    const int g = lane >> 2, tig = lane & 3;
    const int wm = (wid & 1) * 64, wn = (wid >> 1) * 32;
    const int bm = blockIdx.y * BM, bn = blockIdx.x * BN;
    const int NC = K >> 5;

    // staging: quad index tid -> row tid>>3 (+32j), k-quad tid&7 (same for A and BT)
    const int srow = tid >> 3, skq = tid & 7;

    // per-lane ldmatrix offsets (floats, relative to stage A/B bases)
    // A tiles: t=lane>>3 -> {a0,a1,a2,a3}: row = wm + (lane&7) + ((lane>>3)&1)*8,
    //          kcol = (lane>>4)*4  (frag adds mf*16*ASTR + 8s)
    const int aoff = (wm + (lane & 7) + ((lane >> 3) & 1) * 8) * ASTR + (lane >> 4) * 4;
    // B tiles: t=lane>>3 -> {b0[nf],b1[nf],b0[nf+1],b1[nf+1]}:
    //          row = wn + (lane&7) + (lane>>4)*8, kcol = ((lane>>3)&1)*4
    const int boff = (wn + (lane & 7) + (lane >> 4) * 8) * BSTR + ((lane >> 3) & 1) * 4;

    float acc[4][4][4];
#pragma unroll
    for (int i = 0; i < 4; i++)
#pragma unroll
        for (int j = 0; j < 4; j++)
#pragma unroll
            for (int r = 0; r < 4; r++) acc[i][j][r] = 0.f;

#define LOADST(chunk, stage) do {                                               \
        const int kb = (chunk) * BK;                                            \
        const uint32_t sA = sb + (stage) * (STAGE_F * 4);                       \
        const uint32_t sB = sA + A_STAGE * 4;                                   \
        _Pragma("unroll")                                                       \
        for (int j = 0; j < 4; j++) {                                           \
            const int r = srow + 32 * j;                                        \
            cp_async16(sA + (r * ASTR + skq * 4) * 4,                           \
                       A + (size_t)(bm + r) * lda + kb + skq * 4);              \
            cp_async16(sB + (r * BSTR + skq * 4) * 4,                           \
                       BT + (size_t)(bn + r) * ldbt + kb + skq * 4);            \
        }                                                                       \
        cp_commit();                                                            \
    } while (0)

    LOADST(0, 0);
    if (NC > 1) LOADST(1, 1);

    for (int i = 0; i < NC; i++) {
        if (i + 2 < NC) asm volatile("cp.async.wait_group 1;\n" ::: "memory");
        else            asm volatile("cp.async.wait_group 0;\n" ::: "memory");
        __syncthreads();
        if (i + 2 < NC) {
            int st = i + 2;
            st = st - (st / NSTAGE) * NSTAGE;
            LOADST(i + 2, st);
        }

        const int stage = i - (i / NSTAGE) * NSTAGE;
        const uint32_t aBase = sb + stage * (STAGE_F * 4);
        const uint32_t bBase = aBase + A_STAGE * 4;
#pragma unroll
        for (int s = 0; s < 4; s++) {
            uint32_t af[4][4], bf[4][2];
#pragma unroll
            for (int mf = 0; mf < 4; mf++)
                LDSM_X4(af[mf], aBase + (uint32_t)(aoff + mf * (16 * ASTR) + 8 * s) * 4);
            LDSM_X4(bf[0], bBase + (uint32_t)(boff + 8 * s) * 4);
            LDSM_X4(bf[2], bBase + (uint32_t)(boff + 16 * BSTR + 8 * s) * 4);
#pragma unroll
            for (int mf = 0; mf < 4; mf++)
#pragma unroll
                for (int nf = 0; nf < 4; nf++)
                    MMA_TF32(acc[mf][nf], af[mf], bf[nf]);
        }
    }

    // epilogue
#pragma unroll
    for (int mf = 0; mf < 4; mf++) {
        const int row0 = bm + wm + 16 * mf + g;
#pragma unroll
        for (int nf = 0; nf < 4; nf++) {
            const int col = bn + wn + 8 * nf + 2 * tig;
            if (col < Nvalid) {
                float4 vals = make_float4(acc[mf][nf][0], acc[mf][nf][1],
                                          acc[mf][nf][2], acc[mf][nf][3]);
                if (col < round_limit) {
                    vals.x = rna_tf32(vals.x); vals.y = rna_tf32(vals.y);
                    vals.z = rna_tf32(vals.z); vals.w = rna_tf32(vals.w);
                }
                *reinterpret_cast<float2*>(C + (size_t)row0 * ldc + col) =
                    make_float2(vals.x, vals.y);
                *reinterpret_cast<float2*>(C + (size_t)(row0 + 8) * ldc + col) =
                    make_float2(vals.z, vals.w);
            }
        }
    }
}

// ---------------- prep kernels ------------------------------------------------
__global__ void prep_w4(const float4* __restrict__ in, float4* __restrict__ out, int n4) {
    const int i = blockIdx.x * 256 + threadIdx.x;
    if (i >= n4) return;
    float4 v = in[i];
    v.x = rna_tf32(v.x); v.y = rna_tf32(v.y);
    v.z = rna_tf32(v.z); v.w = rna_tf32(v.w);
    out[i] = v;
}

// out[c][r] = rna(in[r][c]); in is [R, C] row-major, out is [C, R] row-major
__global__ void transpose_rna(const float* __restrict__ in, float* __restrict__ out,
                              int R, int C) {
    __shared__ float t[32][33];
    const int r0 = blockIdx.x * 32, c0 = blockIdx.y * 32;
    const int x = threadIdx.x, y = threadIdx.y;
    for (int i = y; i < 32; i += 8) {
        const int r = r0 + i, c = c0 + x;
        t[i][x] = (r < R && c < C) ? rna_tf32(in[(size_t)r * C + c]) : 0.f;
    }
    __syncthreads();
    for (int i = y; i < 32; i += 8) {
        const int c = c0 + i, r = r0 + x;
        if (c < C && r < R) out[(size_t)c * R + r] = t[x][i];
    }
}

// ---------------- depthwise causal conv (K=4) + SiLU (+ scale) --------------
__global__ __launch_bounds__(256) void conv_silu_k(const float* __restrict__ x,
                                                   const float* __restrict__ w,
                                                   float* __restrict__ y, float scale) {
    const int idx = blockIdx.x * 256 + threadIdx.x;
    const int t = idx >> 12;
    const int p = idx & (PP - 1);
    const size_t xi = (size_t)t * NQKV + p;
    const float4 wv = *reinterpret_cast<const float4*>(w + p * 4);
    float acc = x[xi] * wv.w;
    if (t >= 1) acc += x[xi - NQKV] * wv.z;
    if (t >= 2) acc += x[xi - 2 * NQKV] * wv.y;
    if (t >= 3) acc += x[xi - 3 * NQKV] * wv.x;
    const float sg = 1.f / (1.f + expf(-acc));
    y[idx] = acc * sg * scale;
}

__global__ void beta_k(const float* __restrict__ fab, float* __restrict__ b) {
    const int idx = blockIdx.x * 256 + threadIdx.x;
    if (idx >= TT * NH) return;
    const int t = idx >> 5, h = idx & 31;
    const float x = fab[(size_t)t * NFAB + 256 + h];
    b[idx] = 2.f / (1.f + expf(-x));
}

__global__ __launch_bounds__(256) void gate_k(float* __restrict__ g,
                                              const float* __restrict__ dt_bias,
                                              const float* __restrict__ A_log) {
    const int idx = blockIdx.x * 256 + threadIdx.x;
    const int p = idx & (PP - 1);
    const int h = p >> 7;
    const float a = expf(A_log[h]);
    const float x = g[idx] + dt_bias[p];
    const float sg = 1.f / (1.f + expf(-a * x));
    g[idx] = expf(-5.f * sg);
}

// ---------------- KDA scan ----------------------------------------------------
struct Step { float k[16], q[16], e[16]; float v, b; };

__device__ __forceinline__ void ld16(float* d, const float* s) {
    float4 v0 = *reinterpret_cast<const float4*>(s);
    float4 v1 = *reinterpret_cast<const float4*>(s + 4);
    float4 v2 = *reinterpret_cast<const float4*>(s + 8);
    float4 v3 = *reinterpret_cast<const float4*>(s + 12);
    d[0] = v0.x; d[1] = v0.y; d[2]  = v0.z; d[3]  = v0.w;
    d[4] = v1.x; d[5] = v1.y; d[6]  = v1.z; d[7]  = v1.w;
    d[8] = v2.x; d[9] = v2.y; d[10] = v2.z; d[11] = v2.w;
    d[12] = v3.x; d[13] = v3.y; d[14] = v3.z; d[15] = v3.w;
}

__device__ __forceinline__ void fetch_step(Step& st, int t, int off_kqe, int off_v, int h,
                                           const float* __restrict__ q,
                                           const float* __restrict__ k,
                                           const float* __restrict__ v,
                                           const float* __restrict__ eg,
                                           const float* __restrict__ beta) {
    const int base = t * PP;
    ld16(st.k, k + base + off_kqe);
    ld16(st.q, q + base + off_kqe);
    ld16(st.e, eg + base + off_kqe);
    st.v = v[base + off_v];
    st.b = beta[t * NH + h];
}

__device__ __forceinline__ void do_step(float* S, const Step& st,
                                        float* __restrict__ o, int t, int off_v, int s) {
    float p0 = 0.f, p1 = 0.f;
#pragma unroll
    for (int r = 0; r < 16; r += 2) {
        S[r]     *= st.e[r];     p0 += S[r]     * st.k[r];
        S[r + 1] *= st.e[r + 1]; p1 += S[r + 1] * st.k[r + 1];
    }
    float part = p0 + p1;
    part += __shfl_xor_sync(0xffffffffu, part, 1);
    part += __shfl_xor_sync(0xffffffffu, part, 2);
    part += __shfl_xor_sync(0xffffffffu, part, 4);
    const float u = st.b * (st.v - part);
    float o0 = 0.f, o1 = 0.f;
#pragma unroll
    for (int r = 0; r < 16; r += 2) {
        S[r]     += st.k[r] * u;     o0 += st.q[r]     * S[r];
        S[r + 1] += st.k[r + 1] * u; o1 += st.q[r + 1] * S[r + 1];
    }
    float po = o0 + o1;
    po += __shfl_xor_sync(0xffffffffu, po, 1);
    po += __shfl_xor_sync(0xffffffffu, po, 2);
    po += __shfl_xor_sync(0xffffffffu, po, 4);
    if (s == 0) o[t * PP + off_v] = po;
}

__global__ __launch_bounds__(256) void scan_k(const float* __restrict__ q,
                                              const float* __restrict__ k,
                                              const float* __restrict__ v,
                                              const float* __restrict__ eg,
                                              const float* __restrict__ beta,
                                              float* __restrict__ o) {
    const int h = blockIdx.y;
    const int jl = threadIdx.x >> 3;
    const int s = threadIdx.x & 7;
    const int j = blockIdx.x * 32 + jl;
    const int off_kqe = h * HD + s * 16;
    const int off_v = h * HD + j;

    float S[16];
#pragma unroll
    for (int r = 0; r < 16; r++) S[r] = 0.f;

    Step A, B;
    fetch_step(A, 0, off_kqe, off_v, h, q, k, v, eg, beta);
    for (int t = 0; t < TT; t += 2) {
        fetch_step(B, t + 1, off_kqe, off_v, h, q, k, v, eg, beta);
        do_step(S, A, o, t, off_v, s);
        const int t2 = (t + 2 < TT) ? (t + 2) : (TT - 1);
        fetch_step(A, t2, off_kqe, off_v, h, q, k, v, eg, beta);
        do_step(S, B, o, t + 1, off_v, s);
    }
}

// ---------------- gated RMSNorm (rounds output for Wo GEMM) -------------------
__global__ __launch_bounds__(256) void rmsnorm_k(float* __restrict__ o,
                                                 const float* __restrict__ g2,
                                                 const float* __restrict__ w) {
    const int warp = (blockIdx.x * blockDim.x + threadIdx.x) >> 5;
    const int lane = threadIdx.x & 31;
    if (warp >= TT * NH) return;
    const int base = warp * HD + lane * 4;
    float4 x = *reinterpret_cast<const float4*>(o + base);
    float ss = x.x * x.x + x.y * x.y + x.z * x.z + x.w * x.w;
#pragma unroll
    for (int d = 16; d > 0; d >>= 1) ss += __shfl_xor_sync(0xffffffffu, ss, d);
    const float rstd = rsqrtf(ss * (1.f / 128.f) + 1e-5f);
    const float4 g = *reinterpret_cast<const float4*>(g2 + base);
    const float4 wv = *reinterpret_cast<const float4*>(w + lane * 4);
    float4 r;
    r.x = rna_tf32(x.x * rstd * wv.x / (1.f + expf(-g.x)));
    r.y = rna_tf32(x.y * rstd * wv.y / (1.f + expf(-g.y)));
    r.z = rna_tf32(x.z * rstd * wv.z / (1.f + expf(-g.z)));
    r.w = rna_tf32(x.w * rstd * wv.w / (1.f + expf(-g.w)));
    *reinterpret_cast<float4*>(o + base) = r;
}

// ---------------- launch --------------------------------------------------------
extern "C" void kernel_launch(void* const* d_in, const int* in_sizes, int n_in,
                              void* d_out, int out_size) {
    const float* hs   = (const float*)d_in[0];
    const float* Wq   = (const float*)d_in[1];
    const float* Wk   = (const float*)d_in[2];
    const float* Wv   = (const float*)d_in[3];
    const float* cq   = (const float*)d_in[4];
    const float* ck   = (const float*)d_in[5];
    const float* cv   = (const float*)d_in[6];
    const float* Wb   = (const float*)d_in[7];
    const float* Wfa  = (const float*)d_in[8];
    const float* Wfb  = (const float*)d_in[9];
    const float* dtb  = (const float*)d_in[10];
    const float* Alog = (const float*)d_in[11];
    const float* Wga  = (const float*)d_in[12];
    const float* Wgb  = (const float*)d_in[13];
    const float* onw  = (const float*)d_in[14];
    const float* Wo   = (const float*)d_in[15];
    float* out = (float*)d_out;

    float *hsr, *qkvp, *q, *k, *v, *eg, *g2, *o, *fab, *beta;
    float *wqkvT, *wfabT, *wfbT, *wgbT, *woT;
    cudaGetSymbolAddress((void**)&hsr, g_hsr);
    cudaGetSymbolAddress((void**)&qkvp, g_qkvp);
    cudaGetSymbolAddress((void**)&q,  g_q);
    cudaGetSymbolAddress((void**)&k,  g_k);
    cudaGetSymbolAddress((void**)&v,  g_v);
    cudaGetSymbolAddress((void**)&eg, g_eg);
    cudaGetSymbolAddress((void**)&g2, g_g2);
    cudaGetSymbolAddress((void**)&o,  g_o);
    cudaGetSymbolAddress((void**)&fab, g_fab);
    cudaGetSymbolAddress((void**)&beta, g_beta);
    cudaGetSymbolAddress((void**)&wqkvT, g_wqkvT);
    cudaGetSymbolAddress((void**)&wfabT, g_wfabT);
    cudaGetSymbolAddress((void**)&wfbT, g_wfbT);
    cudaGetSymbolAddress((void**)&wgbT, g_wgbT);
    cudaGetSymbolAddress((void**)&woT, g_woT);

    cudaFuncSetAttribute(mma_gemm, cudaFuncAttributeMaxDynamicSharedMemorySize, GEMM_SMEM);

    const dim3 blk(256);
    const dim3 tb(32, 8);

    // 1-4: hs round + QKV weight transposes
    prep_w4<<<(TT * HID / 4 + 255) / 256, blk>>>((const float4*)hs, (float4*)hsr, TT * HID / 4);
    transpose_rna<<<dim3(64, 128), tb>>>(Wq, wqkvT,                  HID, PP);
    transpose_rna<<<dim3(64, 128), tb>>>(Wk, wqkvT + (size_t)PP * HID,     HID, PP);
    transpose_rna<<<dim3(64, 128), tb>>>(Wv, wqkvT + (size_t)2 * PP * HID, HID, PP);

    // 5-6: the two fused-QKV GEMM halves (profiling window)
    mma_gemm<<<dim3(48, 32), blk, GEMM_SMEM>>>(hsr, HID, wqkvT, HID, qkvp, NQKV,
                                               NQKV / 2, HID, 0);
    mma_gemm<<<dim3(48, 32), blk, GEMM_SMEM>>>(hsr, HID, wqkvT + (size_t)(NQKV / 2) * HID,
                                               HID, qkvp + NQKV / 2, NQKV,
                                               NQKV / 2, HID, 0);

    // fab weight transposes (into row slices of wfabT) + fused fa/ga/beta GEMM
    transpose_rna<<<dim3(64, 4), tb>>>(Wfa, wfabT,               HID, HD);
    transpose_rna<<<dim3(64, 4), tb>>>(Wga, wfabT + HD * HID,    HID, HD);
    transpose_rna<<<dim3(64, 1), tb>>>(Wb,  wfabT + 2 * HD * HID, HID, NH);
    mma_gemm<<<dim3(3, 32), blk, GEMM_SMEM>>>(hsr, HID, wfabT, HID, fab, NFAB,
                                              288, HID, 256);

    // convs + beta
    conv_silu_k<<<TP / 256, blk>>>(qkvp,          cq, q, 0.08838834764831845f);
    conv_silu_k<<<TP / 256, blk>>>(qkvp + PP,     ck, k, 1.f);
    conv_silu_k<<<TP / 256, blk>>>(qkvp + 2 * PP, cv, v, 1.f);
    beta_k<<<(TT * NH + 255) / 256, blk>>>(fab, beta);

    // gate GEMMs (A = fa / ga slices of fab, BT = transposed low-rank weights)
    transpose_rna<<<dim3(4, 128), tb>>>(Wfb, wfbT, HD, PP);
    mma_gemm<<<dim3(32, 32), blk, GEMM_SMEM>>>(fab, NFAB, wfbT, HD, eg, PP, PP, HD, 0);
    gate_k<<<TP / 256, blk>>>(eg, dtb, Alog);
    transpose_rna<<<dim3(4, 128), tb>>>(Wgb, wgbT, HD, PP);
    mma_gemm<<<dim3(32, 32), blk, GEMM_SMEM>>>(fab + 128, NFAB, wgbT, HD, g2, PP, PP, HD, 0);

    // sequential KDA scan
    scan_k<<<dim3(4, NH), blk>>>(q, k, v, eg, beta, o);

    // gated rmsnorm + output projection
    rmsnorm_k<<<(TT * NH * 32) / 256, blk>>>(o, g2, onw);
    transpose_rna<<<dim3(128, 64), tb>>>(Wo, woT, PP, HID);
    mma_gemm<<<dim3(16, 32), blk, GEMM_SMEM>>>(o, PP, woT, PP, out, HID, HID, PP, 0);
}

// round 7
// speedup vs baseline: 1.5253x; 1.5253x over previous
#include <cuda_runtime.h>
#include <math.h>
#include <stdint.h>

#define TT   4096
#define HID  2048
#define NH   32
#define HD   128
#define PP   4096
#define TP   (TT * PP)
#define NQKV 12288    // 3*PP
#define NFAB 384      // fa(128) | ga(128) | beta(32 pad->128)

// ---------------- scratch (device globals; no allocations allowed) ----------
__device__ float g_hsr[TT * HID];
__device__ float g_qkvp[TT * NQKV];
__device__ float g_q [TP];
__device__ float g_k [TP];
__device__ float g_v [TP];
__device__ float g_eg[TP];
__device__ float g_g2[TP];
__device__ float g_o [TP];
__device__ float g_fab[TT * NFAB];
__device__ float g_beta[TT * NH];
// rounded (+padded/concatenated) weights
__device__ float g_wqkvR[HID * NQKV];
__device__ float g_wfabR[HID * NFAB];
__device__ float g_wfbR[HD * PP];
__device__ float g_wgbR[HD * PP];
__device__ float g_woR[PP * HID];

// ---------------- helpers -----------------------------------------------------
__device__ __forceinline__ uint32_t smem_u32(const void* p) {
    uint32_t a;
    asm("{ .reg .u64 t; cvta.to.shared.u64 t, %1; cvt.u32.u64 %0, t; }" : "=r"(a) : "l"(p));
    return a;
}
__device__ __forceinline__ float rna_tf32(float x) {
    uint32_t o, i = __float_as_uint(x);
    asm("cvt.rna.tf32.f32 %0, %1;" : "=r"(o) : "r"(i));
    return __uint_as_float(o);
}
__device__ __forceinline__ void cp_async16(uint32_t dst, const float* src) {
    asm volatile("cp.async.cg.shared.global [%0], [%1], 16;\n"
                 :: "r"(dst), "l"(__cvta_generic_to_global(src)));
}
__device__ __forceinline__ void cp_commit() { asm volatile("cp.async.commit_group;\n" ::: "memory"); }

#define MMA_TF32(d, a, b)                                                      \
    asm volatile("mma.sync.aligned.m16n8k8.row.col.f32.tf32.tf32.f32 "        \
                 "{%0,%1,%2,%3}, {%4,%5,%6,%7}, {%8,%9}, {%0,%1,%2,%3};"      \
                 : "+f"((d)[0]), "+f"((d)[1]), "+f"((d)[2]), "+f"((d)[3])     \
                 : "r"((a)[0]), "r"((a)[1]), "r"((a)[2]), "r"((a)[3]),        \
                   "r"((b)[0]), "r"((b)[1]))

#define LDSM_X4(r, addr)                                                       \
    asm volatile("ldmatrix.sync.aligned.m8n8.x4.shared.b16 {%0,%1,%2,%3}, [%4];" \
                 : "=r"((r)[0]), "=r"((r)[1]), "=r"((r)[2]), "=r"((r)[3])      \
                 : "r"(addr))

// ---------------- tf32 mma.sync GEMM ------------------------------------------
// C[M, :Nvalid] (stride ldc) = A[M,K] (stride lda) @ B[K, :] (stride ldb).
// All inputs pre-rounded tf32. CTA tile 128x128x32, 8 warps, 3-stage cp.async.
// A-fragments loaded via ldmatrix.x4 (layout [m][k], stride ASTR); B scalar LDS.
#define BM 128
#define BN 128
#define BK 32
#define ASTR 36
#define BSTR 136
#define A_STAGE (BM * ASTR)
#define B_STAGE (BK * BSTR)
#define STAGE_F (A_STAGE + B_STAGE)
#define NSTAGE 3
#define GEMM_SMEM (NSTAGE * STAGE_F * 4)

__global__ __launch_bounds__(256, 2) void mma_gemm(const float* __restrict__ A, int lda,
                                                   const float* __restrict__ B, int ldb,
                                                   float* __restrict__ C, int ldc,
                                                   int Nvalid, int K, int round_limit) {
    extern __shared__ float sm[];
    const uint32_t sb = smem_u32(sm);

    const int tid = threadIdx.x;
    const int wid = tid >> 5, lane = tid & 31;
    const int g = lane >> 2, tig = lane & 3;
    const int wm = (wid & 1) * 64, wn = (wid >> 1) * 32;
    const int bm = blockIdx.y * BM, bn = blockIdx.x * BN;
    const int NC = K >> 5;

    const int arow = tid >> 3, akq = tid & 7;
    const int brow = tid >> 5, bnq = tid & 31;

    // ldmatrix per-lane offset for A tiles (floats, rel. to stage A base):
    // tile t = lane>>3 -> regs {(m0-7,k0-3),(m8-15,k0-3),(m0-7,k4-7),(m8-15,k4-7)}
    const int aoff = (wm + (lane & 7) + ((lane >> 3) & 1) * 8) * ASTR + (lane >> 4) * 4;

    float acc[4][4][4];
#pragma unroll
    for (int i = 0; i < 4; i++)
#pragma unroll
        for (int j = 0; j < 4; j++)
#pragma unroll
            for (int r = 0; r < 4; r++) acc[i][j][r] = 0.f;

#define LOADST(chunk, stage) do {                                               \
        const int kb = (chunk) * BK;                                            \
        const uint32_t sA = sb + (stage) * STAGE_F * 4;                         \
        const uint32_t sB = sA + A_STAGE * 4;                                   \
        _Pragma("unroll")                                                       \
        for (int j = 0; j < 4; j++) {                                           \
            const int r = arow + 32 * j;                                        \
            cp_async16(sA + (r * ASTR + akq * 4) * 4,                           \
                       A + (size_t)(bm + r) * lda + kb + akq * 4);              \
        }                                                                       \
        _Pragma("unroll")                                                       \
        for (int j = 0; j < 4; j++) {                                           \
            const int r = brow + 8 * j;                                         \
            cp_async16(sB + (r * BSTR + bnq * 4) * 4,                           \
                       B + (size_t)(kb + r) * ldb + bn + bnq * 4);              \
        }                                                                       \
        cp_commit();                                                            \
    } while (0)

    LOADST(0, 0);
    if (NC > 1) LOADST(1, 1);

    for (int i = 0; i < NC; i++) {
        if (i + 2 < NC) asm volatile("cp.async.wait_group 1;\n" ::: "memory");
        else            asm volatile("cp.async.wait_group 0;\n" ::: "memory");
        __syncthreads();
        if (i + 2 < NC) {
            int st = i + 2;
            st = st - (st / NSTAGE) * NSTAGE;
            LOADST(i + 2, st);
        }

        const int stage = i - (i / NSTAGE) * NSTAGE;
        const uint32_t aBase = sb + stage * (STAGE_F * 4);
        const float* bb = sm + stage * STAGE_F + A_STAGE;
#pragma unroll
        for (int s = 0; s < 4; s++) {
            uint32_t af[4][4], bf[4][2];
            const int kk = 8 * s + tig;
#pragma unroll
            for (int mf = 0; mf < 4; mf++)
                LDSM_X4(af[mf], aBase + (uint32_t)(aoff + mf * (16 * ASTR) + 8 * s) * 4);
            const float* brow0 = bb + kk * BSTR + wn;
#pragma unroll
            for (int nf = 0; nf < 4; nf++) {
                bf[nf][0] = __float_as_uint(brow0[8 * nf + g]);
                bf[nf][1] = __float_as_uint(brow0[8 * nf + g + 4 * BSTR]);
            }
#pragma unroll
            for (int mf = 0; mf < 4; mf++)
#pragma unroll
                for (int nf = 0; nf < 4; nf++)
                    MMA_TF32(acc[mf][nf], af[mf], bf[nf]);
        }
    }

    // epilogue
#pragma unroll
    for (int mf = 0; mf < 4; mf++) {
        const int row0 = bm + wm + 16 * mf + g;
#pragma unroll
        for (int nf = 0; nf < 4; nf++) {
            const int col = bn + wn + 8 * nf + 2 * tig;
            if (col < Nvalid) {
                float4 vals = make_float4(acc[mf][nf][0], acc[mf][nf][1],
                                          acc[mf][nf][2], acc[mf][nf][3]);
                if (col < round_limit) {
                    vals.x = rna_tf32(vals.x); vals.y = rna_tf32(vals.y);
                    vals.z = rna_tf32(vals.z); vals.w = rna_tf32(vals.w);
                }
                *reinterpret_cast<float2*>(C + (size_t)row0 * ldc + col) =
                    make_float2(vals.x, vals.y);
                *reinterpret_cast<float2*>(C + (size_t)(row0 + 8) * ldc + col) =
                    make_float2(vals.z, vals.w);
            }
        }
    }
}

// ---------------- prep kernels ------------------------------------------------
__global__ void prep_w4(const float4* __restrict__ in, float4* __restrict__ out, int n4) {
    const int i = blockIdx.x * 256 + threadIdx.x;
    if (i >= n4) return;
    float4 v = in[i];
    v.x = rna_tf32(v.x); v.y = rna_tf32(v.y);
    v.z = rna_tf32(v.z); v.w = rna_tf32(v.w);
    out[i] = v;
}

// concat Wq|Wk|Wv -> [HID, 12288], tf32-rounded
__global__ void prep_wqkv(const float4* __restrict__ wq, const float4* __restrict__ wk,
                          const float4* __restrict__ wv, float4* __restrict__ out, int total4) {
    const int i = blockIdx.x * 256 + threadIdx.x;
    if (i >= total4) return;
    const int n4 = i % (NQKV / 4);
    const int row = i / (NQKV / 4);
    const int seg = n4 >> 10;
    const int off = row * (PP / 4) + (n4 & 1023);
    float4 v = (seg == 0) ? wq[off] : (seg == 1) ? wk[off] : wv[off];
    v.x = rna_tf32(v.x); v.y = rna_tf32(v.y);
    v.z = rna_tf32(v.z); v.w = rna_tf32(v.w);
    out[i] = v;
}

// concat Wfa|Wga|Wb(pad) -> [HID, 384], tf32-rounded
__global__ void prep_wfab(const float4* __restrict__ wfa, const float4* __restrict__ wga,
                          const float4* __restrict__ wb, float4* __restrict__ out, int total4) {
    const int i = blockIdx.x * 256 + threadIdx.x;
    if (i >= total4) return;
    const int n4 = i % (NFAB / 4);
    const int row = i / (NFAB / 4);
    float4 v = make_float4(0.f, 0.f, 0.f, 0.f);
    if (n4 < 32)       v = wfa[row * 32 + n4];
    else if (n4 < 64)  v = wga[row * 32 + (n4 - 32)];
    else if (n4 < 72)  v = wb[row * 8 + (n4 - 64)];
    v.x = rna_tf32(v.x); v.y = rna_tf32(v.y);
    v.z = rna_tf32(v.z); v.w = rna_tf32(v.w);
    out[i] = v;
}

// ---------------- depthwise causal conv (K=4) + SiLU (+ scale) --------------
__global__ __launch_bounds__(256) void conv_silu_k(const float* __restrict__ x,
                                                   const float* __restrict__ w,
                                                   float* __restrict__ y, float scale) {
    const int idx = blockIdx.x * 256 + threadIdx.x;
    const int t = idx >> 12;
    const int p = idx & (PP - 1);
    const size_t xi = (size_t)t * NQKV + p;
    const float4 wv = *reinterpret_cast<const float4*>(w + p * 4);
    float acc = x[xi] * wv.w;
    if (t >= 1) acc += x[xi - NQKV] * wv.z;
    if (t >= 2) acc += x[xi - 2 * NQKV] * wv.y;
    if (t >= 3) acc += x[xi - 3 * NQKV] * wv.x;
    const float sg = 1.f / (1.f + expf(-acc));
    y[idx] = acc * sg * scale;
}

__global__ void beta_k(const float* __restrict__ fab, float* __restrict__ b) {
    const int idx = blockIdx.x * 256 + threadIdx.x;
    if (idx >= TT * NH) return;
    const int t = idx >> 5, h = idx & 31;
    const float x = fab[(size_t)t * NFAB + 256 + h];
    b[idx] = 2.f / (1.f + expf(-x));
}

__global__ __launch_bounds__(256) void gate_k(float* __restrict__ g,
                                              const float* __restrict__ dt_bias,
                                              const float* __restrict__ A_log) {
    const int idx = blockIdx.x * 256 + threadIdx.x;
    const int p = idx & (PP - 1);
    const int h = p >> 7;
    const float a = expf(A_log[h]);
    const float x = g[idx] + dt_bias[p];
    const float sg = 1.f / (1.f + expf(-a * x));
    g[idx] = expf(-5.f * sg);
}

// ---------------- KDA scan ----------------------------------------------------
struct Step { float k[16], q[16], e[16]; float v, b; };

__device__ __forceinline__ void ld16(float* d, const float* s) {
    float4 v0 = *reinterpret_cast<const float4*>(s);
    float4 v1 = *reinterpret_cast<const float4*>(s + 4);
    float4 v2 = *reinterpret_cast<const float4*>(s + 8);
    float4 v3 = *reinterpret_cast<const float4*>(s + 12);
    d[0] = v0.x; d[1] = v0.y; d[2]  = v0.z; d[3]  = v0.w;
    d[4] = v1.x; d[5] = v1.y; d[6]  = v1.z; d[7]  = v1.w;
    d[8] = v2.x; d[9] = v2.y; d[10] = v2.z; d[11] = v2.w;
    d[12] = v3.x; d[13] = v3.y; d[14] = v3.z; d[15] = v3.w;
}

__device__ __forceinline__ void fetch_step(Step& st, int t, int off_kqe, int off_v, int h,
                                           const float* __restrict__ q,
                                           const float* __restrict__ k,
                                           const float* __restrict__ v,
                                           const float* __restrict__ eg,
                                           const float* __restrict__ beta) {
    const int base = t * PP;
    ld16(st.k, k + base + off_kqe);
    ld16(st.q, q + base + off_kqe);
    ld16(st.e, eg + base + off_kqe);
    st.v = v[base + off_v];
    st.b = beta[t * NH + h];
}

__device__ __forceinline__ void do_step(float* S, const Step& st,
                                        float* __restrict__ o, int t, int off_v, int s) {
    float p0 = 0.f, p1 = 0.f;
#pragma unroll
    for (int r = 0; r < 16; r += 2) {
        S[r]     *= st.e[r];     p0 += S[r]     * st.k[r];
        S[r + 1] *= st.e[r + 1]; p1 += S[r + 1] * st.k[r + 1];
    }
    float part = p0 + p1;
    part += __shfl_xor_sync(0xffffffffu, part, 1);
    part += __shfl_xor_sync(0xffffffffu, part, 2);
    part += __shfl_xor_sync(0xffffffffu, part, 4);
    const float u = st.b * (st.v - part);
    float o0 = 0.f, o1 = 0.f;
#pragma unroll
    for (int r = 0; r < 16; r += 2) {
        S[r]     += st.k[r] * u;     o0 += st.q[r]     * S[r];
        S[r + 1] += st.k[r + 1] * u; o1 += st.q[r + 1] * S[r + 1];
    }
    float po = o0 + o1;
    po += __shfl_xor_sync(0xffffffffu, po, 1);
    po += __shfl_xor_sync(0xffffffffu, po, 2);
    po += __shfl_xor_sync(0xffffffffu, po, 4);
    if (s == 0) o[t * PP + off_v] = po;
}

__global__ __launch_bounds__(256) void scan_k(const float* __restrict__ q,
                                              const float* __restrict__ k,
                                              const float* __restrict__ v,
                                              const float* __restrict__ eg,
                                              const float* __restrict__ beta,
                                              float* __restrict__ o) {
    const int h = blockIdx.y;
    const int jl = threadIdx.x >> 3;
    const int s = threadIdx.x & 7;
    const int j = blockIdx.x * 32 + jl;
    const int off_kqe = h * HD + s * 16;
    const int off_v = h * HD + j;

    float S[16];
#pragma unroll
    for (int r = 0; r < 16; r++) S[r] = 0.f;

    Step A, B;
    fetch_step(A, 0, off_kqe, off_v, h, q, k, v, eg, beta);
    for (int t = 0; t < TT; t += 2) {
        fetch_step(B, t + 1, off_kqe, off_v, h, q, k, v, eg, beta);
        do_step(S, A, o, t, off_v, s);
        const int t2 = (t + 2 < TT) ? (t + 2) : (TT - 1);
        fetch_step(A, t2, off_kqe, off_v, h, q, k, v, eg, beta);
        do_step(S, B, o, t + 1, off_v, s);
    }
}

// ---------------- gated RMSNorm (rounds output for Wo GEMM) -------------------
__global__ __launch_bounds__(256) void rmsnorm_k(float* __restrict__ o,
                                                 const float* __restrict__ g2,
                                                 const float* __restrict__ w) {
    const int warp = (blockIdx.x * blockDim.x + threadIdx.x) >> 5;
    const int lane = threadIdx.x & 31;
    if (warp >= TT * NH) return;
    const int base = warp * HD + lane * 4;
    float4 x = *reinterpret_cast<const float4*>(o + base);
    float ss = x.x * x.x + x.y * x.y + x.z * x.z + x.w * x.w;
#pragma unroll
    for (int d = 16; d > 0; d >>= 1) ss += __shfl_xor_sync(0xffffffffu, ss, d);
    const float rstd = rsqrtf(ss * (1.f / 128.f) + 1e-5f);
    const float4 g = *reinterpret_cast<const float4*>(g2 + base);
    const float4 wv = *reinterpret_cast<const float4*>(w + lane * 4);
    float4 r;
    r.x = rna_tf32(x.x * rstd * wv.x / (1.f + expf(-g.x)));
    r.y = rna_tf32(x.y * rstd * wv.y / (1.f + expf(-g.y)));
    r.z = rna_tf32(x.z * rstd * wv.z / (1.f + expf(-g.z)));
    r.w = rna_tf32(x.w * rstd * wv.w / (1.f + expf(-g.w)));
    *reinterpret_cast<float4*>(o + base) = r;
}

// ---------------- launch --------------------------------------------------------
extern "C" void kernel_launch(void* const* d_in, const int* in_sizes, int n_in,
                              void* d_out, int out_size) {
    const float* hs   = (const float*)d_in[0];
    const float* Wq   = (const float*)d_in[1];
    const float* Wk   = (const float*)d_in[2];
    const float* Wv   = (const float*)d_in[3];
    const float* cq   = (const float*)d_in[4];
    const float* ck   = (const float*)d_in[5];
    const float* cv   = (const float*)d_in[6];
    const float* Wb   = (const float*)d_in[7];
    const float* Wfa  = (const float*)d_in[8];
    const float* Wfb  = (const float*)d_in[9];
    const float* dtb  = (const float*)d_in[10];
    const float* Alog = (const float*)d_in[11];
    const float* Wga  = (const float*)d_in[12];
    const float* Wgb  = (const float*)d_in[13];
    const float* onw  = (const float*)d_in[14];
    const float* Wo   = (const float*)d_in[15];
    float* out = (float*)d_out;

    float *hsr, *qkvp, *q, *k, *v, *eg, *g2, *o, *fab, *beta;
    float *wqkvR, *wfabR, *wfbR, *wgbR, *woR;
    cudaGetSymbolAddress((void**)&hsr, g_hsr);
    cudaGetSymbolAddress((void**)&qkvp, g_qkvp);
    cudaGetSymbolAddress((void**)&q,  g_q);
    cudaGetSymbolAddress((void**)&k,  g_k);
    cudaGetSymbolAddress((void**)&v,  g_v);
    cudaGetSymbolAddress((void**)&eg, g_eg);
    cudaGetSymbolAddress((void**)&g2, g_g2);
    cudaGetSymbolAddress((void**)&o,  g_o);
    cudaGetSymbolAddress((void**)&fab, g_fab);
    cudaGetSymbolAddress((void**)&beta, g_beta);
    cudaGetSymbolAddress((void**)&wqkvR, g_wqkvR);
    cudaGetSymbolAddress((void**)&wfabR, g_wfabR);
    cudaGetSymbolAddress((void**)&wfbR, g_wfbR);
    cudaGetSymbolAddress((void**)&wgbR, g_wgbR);
    cudaGetSymbolAddress((void**)&woR, g_woR);

    cudaFuncSetAttribute(mma_gemm, cudaFuncAttributeMaxDynamicSharedMemorySize, GEMM_SMEM);

    const dim3 blk(256);

    // 1-3: preps
    prep_w4<<<(TT * HID / 4 + 255) / 256, blk>>>((const float4*)hs, (float4*)hsr, TT * HID / 4);
    prep_wqkv<<<(HID * NQKV / 4 + 255) / 256, blk>>>((const float4*)Wq, (const float4*)Wk,
                                                     (const float4*)Wv, (float4*)wqkvR,
                                                     HID * NQKV / 4);
    prep_wfab<<<(HID * NFAB / 4 + 255) / 256, blk>>>((const float4*)Wfa, (const float4*)Wga,
                                                     (const float4*)Wb, (float4*)wfabR,
                                                     HID * NFAB / 4);

    // 4-6: GEMMs (profiling window)
    mma_gemm<<<dim3(48, 32), blk, GEMM_SMEM>>>(hsr, HID, wqkvR, NQKV, qkvp, NQKV,
                                               NQKV / 2, HID, 0);
    mma_gemm<<<dim3(48, 32), blk, GEMM_SMEM>>>(hsr, HID, wqkvR + NQKV / 2, NQKV,
                                               qkvp + NQKV / 2, NQKV, NQKV / 2, HID, 0);
    mma_gemm<<<dim3(3, 32), blk, GEMM_SMEM>>>(hsr, HID, wfabR, NFAB, fab, NFAB,
                                              288, HID, 256);

    // convs + beta
    conv_silu_k<<<TP / 256, blk>>>(qkvp,          cq, q, 0.08838834764831845f);
    conv_silu_k<<<TP / 256, blk>>>(qkvp + PP,     ck, k, 1.f);
    conv_silu_k<<<TP / 256, blk>>>(qkvp + 2 * PP, cv, v, 1.f);
    beta_k<<<(TT * NH + 255) / 256, blk>>>(fab, beta);

    // gate GEMMs (A = fa / ga slices of fab)
    prep_w4<<<(HD * PP / 4 + 255) / 256, blk>>>((const float4*)Wfb, (float4*)wfbR, HD * PP / 4);
    mma_gemm<<<dim3(32, 32), blk, GEMM_SMEM>>>(fab, NFAB, wfbR, PP, eg, PP, PP, HD, 0);
    gate_k<<<TP / 256, blk>>>(eg, dtb, Alog);
    prep_w4<<<(HD * PP / 4 + 255) / 256, blk>>>((const float4*)Wgb, (float4*)wgbR, HD * PP / 4);
    mma_gemm<<<dim3(32, 32), blk, GEMM_SMEM>>>(fab + 128, NFAB, wgbR, PP, g2, PP, PP, HD, 0);

    // sequential KDA scan
    scan_k<<<dim3(4, NH), blk>>>(q, k, v, eg, beta, o);

    // gated rmsnorm + output projection
    rmsnorm_k<<<(TT * NH * 32) / 256, blk>>>(o, g2, onw);
    prep_w4<<<(PP * HID / 4 + 255) / 256, blk>>>((const float4*)Wo, (float4*)woR, PP * HID / 4);
    mma_gemm<<<dim3(16, 32), blk, GEMM_SMEM>>>(o, PP, woR, HID, out, HID, HID, PP, 0);
}

// round 8
// speedup vs baseline: 1.6615x; 1.0893x over previous
#include <cuda_runtime.h>
#include <math.h>
#include <stdint.h>

#define TT   4096
#define HID  2048
#define NH   32
#define HD   128
#define PP   4096
#define TP   (TT * PP)
#define NQKV 12288    // 3*PP
#define NFAB 384      // fa(128) | ga(128) | beta(32 pad->128)

// ---------------- scratch (device globals; no allocations allowed) ----------
__device__ float g_hsr[TT * HID];
__device__ float g_qkvp[TT * NQKV];
__device__ float g_q [TP];
__device__ float g_k [TP];
__device__ float g_v [TP];
__device__ float g_eg[TP];
__device__ float g_g2[TP];
__device__ float g_o [TP];
__device__ float g_fab[TT * NFAB];
__device__ float g_beta[TT * NH];
// rounded (+padded/concatenated) weights
__device__ float g_wqkvR[HID * NQKV];
__device__ float g_wfabR[HID * NFAB];
__device__ float g_wfbR[HD * PP];
__device__ float g_wgbR[HD * PP];
__device__ float g_woR[PP * HID];

// ---------------- helpers -----------------------------------------------------
__device__ __forceinline__ uint32_t smem_u32(const void* p) {
    uint32_t a;
    asm("{ .reg .u64 t; cvta.to.shared.u64 t, %1; cvt.u32.u64 %0, t; }" : "=r"(a) : "l"(p));
    return a;
}
__device__ __forceinline__ float rna_tf32(float x) {
    uint32_t o, i = __float_as_uint(x);
    asm("cvt.rna.tf32.f32 %0, %1;" : "=r"(o) : "r"(i));
    return __uint_as_float(o);
}
__device__ __forceinline__ void cp_async16(uint32_t dst, const float* src) {
    asm volatile("cp.async.cg.shared.global [%0], [%1], 16;\n"
                 :: "r"(dst), "l"(__cvta_generic_to_global(src)));
}
__device__ __forceinline__ void cp_async4(uint32_t dst, const float* src) {
    asm volatile("cp.async.ca.shared.global [%0], [%1], 4;\n"
                 :: "r"(dst), "l"(__cvta_generic_to_global(src)));
}
__device__ __forceinline__ void cp_commit() { asm volatile("cp.async.commit_group;\n" ::: "memory"); }

#define MMA_TF32(d, a, b)                                                      \
    asm volatile("mma.sync.aligned.m16n8k8.row.col.f32.tf32.tf32.f32 "        \
                 "{%0,%1,%2,%3}, {%4,%5,%6,%7}, {%8,%9}, {%0,%1,%2,%3};"      \
                 : "+f"((d)[0]), "+f"((d)[1]), "+f"((d)[2]), "+f"((d)[3])     \
                 : "r"((a)[0]), "r"((a)[1]), "r"((a)[2]), "r"((a)[3]),        \
                   "r"((b)[0]), "r"((b)[1]))

#define LDSM_X4(r, addr)                                                       \
    asm volatile("ldmatrix.sync.aligned.m8n8.x4.shared.b16 {%0,%1,%2,%3}, [%4];" \
                 : "=r"((r)[0]), "=r"((r)[1]), "=r"((r)[2]), "=r"((r)[3])      \
                 : "r"(addr))

// ---------------- tf32 mma.sync GEMM (unchanged from R7 best) -----------------
#define BM 128
#define BN 128
#define BK 32
#define ASTR 36
#define BSTR 136
#define A_STAGE (BM * ASTR)
#define B_STAGE (BK * BSTR)
#define STAGE_F (A_STAGE + B_STAGE)
#define NSTAGE 3
#define GEMM_SMEM (NSTAGE * STAGE_F * 4)

__global__ __launch_bounds__(256, 2) void mma_gemm(const float* __restrict__ A, int lda,
                                                   const float* __restrict__ B, int ldb,
                                                   float* __restrict__ C, int ldc,
                                                   int Nvalid, int K, int round_limit) {
    extern __shared__ float sm[];
    const uint32_t sb = smem_u32(sm);

    const int tid = threadIdx.x;
    const int wid = tid >> 5, lane = tid & 31;
    const int g = lane >> 2, tig = lane & 3;
    const int wm = (wid & 1) * 64, wn = (wid >> 1) * 32;
    const int bm = blockIdx.y * BM, bn = blockIdx.x * BN;
    const int NC = K >> 5;

    const int arow = tid >> 3, akq = tid & 7;
    const int brow = tid >> 5, bnq = tid & 31;
    const int aoff = (wm + (lane & 7) + ((lane >> 3) & 1) * 8) * ASTR + (lane >> 4) * 4;

    float acc[4][4][4];
#pragma unroll
    for (int i = 0; i < 4; i++)
#pragma unroll
        for (int j = 0; j < 4; j++)
#pragma unroll
            for (int r = 0; r < 4; r++) acc[i][j][r] = 0.f;

#define LOADST(chunk, stage) do {                                               \
        const int kb = (chunk) * BK;                                            \
        const uint32_t sA = sb + (stage) * STAGE_F * 4;                         \
        const uint32_t sB = sA + A_STAGE * 4;                                   \
        _Pragma("unroll")                                                       \
        for (int j = 0; j < 4; j++) {                                           \
            const int r = arow + 32 * j;                                        \
            cp_async16(sA + (r * ASTR + akq * 4) * 4,                           \
                       A + (size_t)(bm + r) * lda + kb + akq * 4);              \
        }                                                                       \
        _Pragma("unroll")                                                       \
        for (int j = 0; j < 4; j++) {                                           \
            const int r = brow + 8 * j;                                         \
            cp_async16(sB + (r * BSTR + bnq * 4) * 4,                           \
                       B + (size_t)(kb + r) * ldb + bn + bnq * 4);              \
        }                                                                       \
        cp_commit();                                                            \
    } while (0)

    LOADST(0, 0);
    if (NC > 1) LOADST(1, 1);

    for (int i = 0; i < NC; i++) {
        if (i + 2 < NC) asm volatile("cp.async.wait_group 1;\n" ::: "memory");
        else            asm volatile("cp.async.wait_group 0;\n" ::: "memory");
        __syncthreads();
        if (i + 2 < NC) {
            int st = i + 2;
            st = st - (st / NSTAGE) * NSTAGE;
            LOADST(i + 2, st);
        }

        const int stage = i - (i / NSTAGE) * NSTAGE;
        const uint32_t aBase = sb + stage * (STAGE_F * 4);
        const float* bb = sm + stage * STAGE_F + A_STAGE;
#pragma unroll
        for (int s = 0; s < 4; s++) {
            uint32_t af[4][4], bf[4][2];
            const int kk = 8 * s + tig;
#pragma unroll
            for (int mf = 0; mf < 4; mf++)
                LDSM_X4(af[mf], aBase + (uint32_t)(aoff + mf * (16 * ASTR) + 8 * s) * 4);
            const float* brow0 = bb + kk * BSTR + wn;
#pragma unroll
            for (int nf = 0; nf < 4; nf++) {
                bf[nf][0] = __float_as_uint(brow0[8 * nf + g]);
                bf[nf][1] = __float_as_uint(brow0[8 * nf + g + 4 * BSTR]);
            }
#pragma unroll
            for (int mf = 0; mf < 4; mf++)
#pragma unroll
                for (int nf = 0; nf < 4; nf++)
                    MMA_TF32(acc[mf][nf], af[mf], bf[nf]);
        }
    }

#pragma unroll
    for (int mf = 0; mf < 4; mf++) {
        const int row0 = bm + wm + 16 * mf + g;
#pragma unroll
        for (int nf = 0; nf < 4; nf++) {
            const int col = bn + wn + 8 * nf + 2 * tig;
            if (col < Nvalid) {
                float4 vals = make_float4(acc[mf][nf][0], acc[mf][nf][1],
                                          acc[mf][nf][2], acc[mf][nf][3]);
                if (col < round_limit) {
                    vals.x = rna_tf32(vals.x); vals.y = rna_tf32(vals.y);
                    vals.z = rna_tf32(vals.z); vals.w = rna_tf32(vals.w);
                }
                *reinterpret_cast<float2*>(C + (size_t)row0 * ldc + col) =
                    make_float2(vals.x, vals.y);
                *reinterpret_cast<float2*>(C + (size_t)(row0 + 8) * ldc + col) =
                    make_float2(vals.z, vals.w);
            }
        }
    }
}

// ---------------- prep kernels ------------------------------------------------
__global__ void prep_w4(const float4* __restrict__ in, float4* __restrict__ out, int n4) {
    const int i = blockIdx.x * 256 + threadIdx.x;
    if (i >= n4) return;
    float4 v = in[i];
    v.x = rna_tf32(v.x); v.y = rna_tf32(v.y);
    v.z = rna_tf32(v.z); v.w = rna_tf32(v.w);
    out[i] = v;
}

__global__ void prep_wqkv(const float4* __restrict__ wq, const float4* __restrict__ wk,
                          const float4* __restrict__ wv, float4* __restrict__ out, int total4) {
    const int i = blockIdx.x * 256 + threadIdx.x;
    if (i >= total4) return;
    const int n4 = i % (NQKV / 4);
    const int row = i / (NQKV / 4);
    const int seg = n4 >> 10;
    const int off = row * (PP / 4) + (n4 & 1023);
    float4 v = (seg == 0) ? wq[off] : (seg == 1) ? wk[off] : wv[off];
    v.x = rna_tf32(v.x); v.y = rna_tf32(v.y);
    v.z = rna_tf32(v.z); v.w = rna_tf32(v.w);
    out[i] = v;
}

__global__ void prep_wfab(const float4* __restrict__ wfa, const float4* __restrict__ wga,
                          const float4* __restrict__ wb, float4* __restrict__ out, int total4) {
    const int i = blockIdx.x * 256 + threadIdx.x;
    if (i >= total4) return;
    const int n4 = i % (NFAB / 4);
    const int row = i / (NFAB / 4);
    float4 v = make_float4(0.f, 0.f, 0.f, 0.f);
    if (n4 < 32)       v = wfa[row * 32 + n4];
    else if (n4 < 64)  v = wga[row * 32 + (n4 - 32)];
    else if (n4 < 72)  v = wb[row * 8 + (n4 - 64)];
    v.x = rna_tf32(v.x); v.y = rna_tf32(v.y);
    v.z = rna_tf32(v.z); v.w = rna_tf32(v.w);
    out[i] = v;
}

// ---------------- depthwise causal conv (K=4) + SiLU (+ scale) --------------
__global__ __launch_bounds__(256) void conv_silu_k(const float* __restrict__ x,
                                                   const float* __restrict__ w,
                                                   float* __restrict__ y, float scale) {
    const int idx = blockIdx.x * 256 + threadIdx.x;
    const int t = idx >> 12;
    const int p = idx & (PP - 1);
    const size_t xi = (size_t)t * NQKV + p;
    const float4 wv = *reinterpret_cast<const float4*>(w + p * 4);
    float acc = x[xi] * wv.w;
    if (t >= 1) acc += x[xi - NQKV] * wv.z;
    if (t >= 2) acc += x[xi - 2 * NQKV] * wv.y;
    if (t >= 3) acc += x[xi - 3 * NQKV] * wv.x;
    const float sg = 1.f / (1.f + expf(-acc));
    y[idx] = acc * sg * scale;
}

__global__ void beta_k(const float* __restrict__ fab, float* __restrict__ b) {
    const int idx = blockIdx.x * 256 + threadIdx.x;
    if (idx >= TT * NH) return;
    const int t = idx >> 5, h = idx & 31;
    const float x = fab[(size_t)t * NFAB + 256 + h];
    b[idx] = 2.f / (1.f + expf(-x));
}

__global__ __launch_bounds__(256) void gate_k(float* __restrict__ g,
                                              const float* __restrict__ dt_bias,
                                              const float* __restrict__ A_log) {
    const int idx = blockIdx.x * 256 + threadIdx.x;
    const int p = idx & (PP - 1);
    const int h = p >> 7;
    const float a = expf(A_log[h]);
    const float x = g[idx] + dt_bias[p];
    const float sg = 1.f / (1.f + expf(-a * x));
    g[idx] = expf(-5.f * sg);
}

// ---------------- KDA scan v2: smem-ring cp.async pipeline --------------------
// CTA = (jblock, head): 32 v-columns x 8 state-threads. Ring of 3 buffers,
// 8 steps per block, filled 2 blocks (16 steps) ahead by all threads.
#define SBLK 8                    // steps per block
#define SLOT_F 420                // k128|q128|e128|v32|beta1|pad3
#define BUF_F (SBLK * SLOT_F)     // 3360 floats per buffer
#define SNBUF 3
#define NBLK (TT / SBLK)          // 512

__global__ __launch_bounds__(256) void scan_k(const float* __restrict__ q,
                                              const float* __restrict__ k,
                                              const float* __restrict__ v,
                                              const float* __restrict__ eg,
                                              const float* __restrict__ beta,
                                              float* __restrict__ o) {
    __shared__ float ring[SNBUF * BUF_F];   // 40320 floats = 40.3KB

    const int tid = threadIdx.x;
    const int h = blockIdx.y;
    const int jb = blockIdx.x;              // 0..3
    const int jl = tid >> 3;                // column within block (0..31)
    const int s = tid & 7;                  // state slice (0..7)
    const int off_v = h * HD + jb * 32 + jl;
    const uint32_t ring_u32 = smem_u32(ring);

    const float* kqe_base[3] = {k + h * HD, q + h * HD, eg + h * HD};

    // fill buffer (blk % SNBUF) with steps blk*8 .. blk*8+7
#define SCAN_FILL(blk) do {                                                     \
        const int t0 = (blk) * SBLK;                                            \
        const uint32_t bufb = ring_u32 + ((blk) % SNBUF) * (BUF_F * 4);         \
        for (int u = tid; u < SBLK * 104; u += 256) {                           \
            const int st = u / 104;                                             \
            const int item = u - st * 104;                                      \
            const size_t gbase = (size_t)(t0 + st) * PP;                        \
            const float* src;                                                   \
            if (item < 96) src = kqe_base[item >> 5] + gbase + (item & 31) * 4; \
            else           src = v + gbase + h * HD + jb * 32 + (item - 96) * 4;\
            cp_async16(bufb + (st * SLOT_F + item * 4) * 4, src);               \
        }                                                                       \
        if (tid < SBLK)                                                         \
            cp_async4(bufb + (tid * SLOT_F + 416) * 4,                          \
                      beta + (size_t)(t0 + tid) * NH + h);                      \
        cp_commit();                                                            \
    } while (0)

    float S[16];
#pragma unroll
    for (int r = 0; r < 16; r++) S[r] = 0.f;

    SCAN_FILL(0);
    SCAN_FILL(1);

    for (int b = 0; b < NBLK; b++) {
        if (b < NBLK - 1) asm volatile("cp.async.wait_group 1;\n" ::: "memory");
        else              asm volatile("cp.async.wait_group 0;\n" ::: "memory");
        __syncthreads();
        if (b + 2 < NBLK) SCAN_FILL(b + 2);

        const float* buf = ring + (b % SNBUF) * BUF_F;
#pragma unroll
        for (int si = 0; si < SBLK; si++) {
            const float* slot = buf + si * SLOT_F;
            const float* kp = slot + s * 16;
            const float* qp = slot + 128 + s * 16;
            const float* ep = slot + 256 + s * 16;
            float kf[16], qf[16], ef[16];
#pragma unroll
            for (int r = 0; r < 16; r += 4) {
                float4 kv4 = *reinterpret_cast<const float4*>(kp + r);
                float4 qv4 = *reinterpret_cast<const float4*>(qp + r);
                float4 ev4 = *reinterpret_cast<const float4*>(ep + r);
                kf[r] = kv4.x; kf[r+1] = kv4.y; kf[r+2] = kv4.z; kf[r+3] = kv4.w;
                qf[r] = qv4.x; qf[r+1] = qv4.y; qf[r+2] = qv4.z; qf[r+3] = qv4.w;
                ef[r] = ev4.x; ef[r+1] = ev4.y; ef[r+2] = ev4.z; ef[r+3] = ev4.w;
            }
            const float vt = slot[384 + jl];
            const float bt = slot[416];

            float p0 = 0.f, p1 = 0.f;
#pragma unroll
            for (int r = 0; r < 16; r += 2) {
                S[r]     *= ef[r];     p0 += S[r]     * kf[r];
                S[r + 1] *= ef[r + 1]; p1 += S[r + 1] * kf[r + 1];
            }
            float part = p0 + p1;
            part += __shfl_xor_sync(0xffffffffu, part, 1);
            part += __shfl_xor_sync(0xffffffffu, part, 2);
            part += __shfl_xor_sync(0xffffffffu, part, 4);
            const float u = bt * (vt - part);
            float o0 = 0.f, o1 = 0.f;
#pragma unroll
            for (int r = 0; r < 16; r += 2) {
                S[r]     += kf[r] * u;     o0 += qf[r]     * S[r];
                S[r + 1] += kf[r + 1] * u; o1 += qf[r + 1] * S[r + 1];
            }
            float po = o0 + o1;
            po += __shfl_xor_sync(0xffffffffu, po, 1);
            po += __shfl_xor_sync(0xffffffffu, po, 2);
            po += __shfl_xor_sync(0xffffffffu, po, 4);
            if (s == 0) o[(size_t)(b * SBLK + si) * PP + off_v] = po;
        }
        __syncthreads();
    }
}

// ---------------- gated RMSNorm (rounds output for Wo GEMM) -------------------
__global__ __launch_bounds__(256) void rmsnorm_k(float* __restrict__ o,
                                                 const float* __restrict__ g2,
                                                 const float* __restrict__ w) {
    const int warp = (blockIdx.x * blockDim.x + threadIdx.x) >> 5;
    const int lane = threadIdx.x & 31;
    if (warp >= TT * NH) return;
    const int base = warp * HD + lane * 4;
    float4 x = *reinterpret_cast<const float4*>(o + base);
    float ss = x.x * x.x + x.y * x.y + x.z * x.z + x.w * x.w;
#pragma unroll
    for (int d = 16; d > 0; d >>= 1) ss += __shfl_xor_sync(0xffffffffu, ss, d);
    const float rstd = rsqrtf(ss * (1.f / 128.f) + 1e-5f);
    const float4 g = *reinterpret_cast<const float4*>(g2 + base);
    const float4 wv = *reinterpret_cast<const float4*>(w + lane * 4);
    float4 r;
    r.x = rna_tf32(x.x * rstd * wv.x / (1.f + expf(-g.x)));
    r.y = rna_tf32(x.y * rstd * wv.y / (1.f + expf(-g.y)));
    r.z = rna_tf32(x.z * rstd * wv.z / (1.f + expf(-g.z)));
    r.w = rna_tf32(x.w * rstd * wv.w / (1.f + expf(-g.w)));
    *reinterpret_cast<float4*>(o + base) = r;
}

// ---------------- launch --------------------------------------------------------
extern "C" void kernel_launch(void* const* d_in, const int* in_sizes, int n_in,
                              void* d_out, int out_size) {
    const float* hs   = (const float*)d_in[0];
    const float* Wq   = (const float*)d_in[1];
    const float* Wk   = (const float*)d_in[2];
    const float* Wv   = (const float*)d_in[3];
    const float* cq   = (const float*)d_in[4];
    const float* ck   = (const float*)d_in[5];
    const float* cv   = (const float*)d_in[6];
    const float* Wb   = (const float*)d_in[7];
    const float* Wfa  = (const float*)d_in[8];
    const float* Wfb  = (const float*)d_in[9];
    const float* dtb  = (const float*)d_in[10];
    const float* Alog = (const float*)d_in[11];
    const float* Wga  = (const float*)d_in[12];
    const float* Wgb  = (const float*)d_in[13];
    const float* onw  = (const float*)d_in[14];
    const float* Wo   = (const float*)d_in[15];
    float* out = (float*)d_out;

    float *hsr, *qkvp, *q, *k, *v, *eg, *g2, *o, *fab, *beta;
    float *wqkvR, *wfabR, *wfbR, *wgbR, *woR;
    cudaGetSymbolAddress((void**)&hsr, g_hsr);
    cudaGetSymbolAddress((void**)&qkvp, g_qkvp);
    cudaGetSymbolAddress((void**)&q,  g_q);
    cudaGetSymbolAddress((void**)&k,  g_k);
    cudaGetSymbolAddress((void**)&v,  g_v);
    cudaGetSymbolAddress((void**)&eg, g_eg);
    cudaGetSymbolAddress((void**)&g2, g_g2);
    cudaGetSymbolAddress((void**)&o,  g_o);
    cudaGetSymbolAddress((void**)&fab, g_fab);
    cudaGetSymbolAddress((void**)&beta, g_beta);
    cudaGetSymbolAddress((void**)&wqkvR, g_wqkvR);
    cudaGetSymbolAddress((void**)&wfabR, g_wfabR);
    cudaGetSymbolAddress((void**)&wfbR, g_wfbR);
    cudaGetSymbolAddress((void**)&wgbR, g_wgbR);
    cudaGetSymbolAddress((void**)&woR, g_woR);

    cudaFuncSetAttribute(mma_gemm, cudaFuncAttributeMaxDynamicSharedMemorySize, GEMM_SMEM);

    const dim3 blk(256);

    // preps
    prep_w4<<<(TT * HID / 4 + 255) / 256, blk>>>((const float4*)hs, (float4*)hsr, TT * HID / 4);
    prep_wqkv<<<(HID * NQKV / 4 + 255) / 256, blk>>>((const float4*)Wq, (const float4*)Wk,
                                                     (const float4*)Wv, (float4*)wqkvR,
                                                     HID * NQKV / 4);
    prep_wfab<<<(HID * NFAB / 4 + 255) / 256, blk>>>((const float4*)Wfa, (const float4*)Wga,
                                                     (const float4*)Wb, (float4*)wfabR,
                                                     HID * NFAB / 4);

    // GEMMs
    mma_gemm<<<dim3(48, 32), blk, GEMM_SMEM>>>(hsr, HID, wqkvR, NQKV, qkvp, NQKV,
                                               NQKV / 2, HID, 0);
    mma_gemm<<<dim3(48, 32), blk, GEMM_SMEM>>>(hsr, HID, wqkvR + NQKV / 2, NQKV,
                                               qkvp + NQKV / 2, NQKV, NQKV / 2, HID, 0);
    mma_gemm<<<dim3(3, 32), blk, GEMM_SMEM>>>(hsr, HID, wfabR, NFAB, fab, NFAB,
                                              288, HID, 256);

    // convs + beta
    conv_silu_k<<<TP / 256, blk>>>(qkvp,          cq, q, 0.08838834764831845f);
    conv_silu_k<<<TP / 256, blk>>>(qkvp + PP,     ck, k, 1.f);
    conv_silu_k<<<TP / 256, blk>>>(qkvp + 2 * PP, cv, v, 1.f);
    beta_k<<<(TT * NH + 255) / 256, blk>>>(fab, beta);

    // gate GEMMs
    prep_w4<<<(HD * PP / 4 + 255) / 256, blk>>>((const float4*)Wfb, (float4*)wfbR, HD * PP / 4);
    mma_gemm<<<dim3(32, 32), blk, GEMM_SMEM>>>(fab, NFAB, wfbR, PP, eg, PP, PP, HD, 0);
    gate_k<<<TP / 256, blk>>>(eg, dtb, Alog);
    prep_w4<<<(HD * PP / 4 + 255) / 256, blk>>>((const float4*)Wgb, (float4*)wgbR, HD * PP / 4);
    mma_gemm<<<dim3(32, 32), blk, GEMM_SMEM>>>(fab + 128, NFAB, wgbR, PP, g2, PP, PP, HD, 0);

    // sequential KDA scan (smem-ring pipelined)
    scan_k<<<dim3(4, NH), blk>>>(q, k, v, eg, beta, o);

    // gated rmsnorm + output projection
    rmsnorm_k<<<(TT * NH * 32) / 256, blk>>>(o, g2, onw);
    prep_w4<<<(PP * HID / 4 + 255) / 256, blk>>>((const float4*)Wo, (float4*)woR, PP * HID / 4);
    mma_gemm<<<dim3(16, 32), blk, GEMM_SMEM>>>(o, PP, woR, HID, out, HID, HID, PP, 0);
}